// round 1
// baseline (speedup 1.0000x reference)
#include <cuda_runtime.h>
#include <cuda_bf16.h>
#include <math.h>

// Problem constants
#define B_SZ 32
#define N_SEQ 512
#define D_MODEL 512
#define DEPTH 147
#define HEADS 8
#define DH (DEPTH * HEADS)          // 1176
#define M_ROWS (B_SZ * N_SEQ)       // 16384
#define QK_COLS (2 * DH)            // 2352

// Scratch (allocation-free rule: __device__ globals)
__device__ float g_C1[(size_t)M_ROWS * QK_COLS];   // q|k projections, 154 MB
__device__ float g_Vp[(size_t)M_ROWS * DH];        // v projection,    77 MB

// ---------------------------------------------------------------------------
// Tiled fp32 GEMM: C[M,N] = A[M,K] @ W[K,N] (+ bias)
// BM=128, BN=64, BK=8, 256 threads, 8x4 micro-tile per thread.
// M % 128 == 0, K % 8 == 0, N % 4 == 0 assumed (true for all three GEMMs).
// ---------------------------------------------------------------------------
#define BM 128
#define BN 64
#define BK 8

__global__ __launch_bounds__(256) void gemm_kernel(
    const float* __restrict__ A, const float* __restrict__ W,
    float* __restrict__ C, int M, int N, int K,
    const float* __restrict__ bias)
{
    __shared__ float As[BK][BM];   // transposed A tile
    __shared__ float Bs[BK][BN];

    const int tid = threadIdx.x;
    const int bm = blockIdx.y * BM;
    const int bn = blockIdx.x * BN;

    const int tm = (tid >> 4) * 8;        // 0..120
    const int tn = (tid & 15) * 4;        // 0..60

    // A load mapping: each thread one float4 (row = tid/2, 4 k's)
    const int arow = tid >> 1;
    const int acol = (tid & 1) * 4;
    // B load mapping: threads 0..127 load one float4 (krow = tid/16)
    const int brow = tid >> 4;
    const int bcol = (tid & 15) * 4;

    float acc[8][4];
#pragma unroll
    for (int i = 0; i < 8; i++)
#pragma unroll
        for (int j = 0; j < 4; j++) acc[i][j] = 0.0f;

    for (int k0 = 0; k0 < K; k0 += BK) {
        // global loads into registers
        float4 av = *(const float4*)(A + (size_t)(bm + arow) * K + k0 + acol);
        float4 bv = make_float4(0.f, 0.f, 0.f, 0.f);
        if (tid < 128) {
            if (bn + bcol < N)
                bv = *(const float4*)(W + (size_t)(k0 + brow) * N + bn + bcol);
        }

        __syncthreads();   // previous tile's compute done before smem overwrite
        As[acol + 0][arow] = av.x;
        As[acol + 1][arow] = av.y;
        As[acol + 2][arow] = av.z;
        As[acol + 3][arow] = av.w;
        if (tid < 128)
            *(float4*)&Bs[brow][bcol] = bv;
        __syncthreads();

#pragma unroll
        for (int kk = 0; kk < BK; kk++) {
            float4 a0 = *(const float4*)&As[kk][tm];
            float4 a1 = *(const float4*)&As[kk][tm + 4];
            float4 b  = *(const float4*)&Bs[kk][tn];
            float ar[8] = {a0.x, a0.y, a0.z, a0.w, a1.x, a1.y, a1.z, a1.w};
            float br[4] = {b.x, b.y, b.z, b.w};
#pragma unroll
            for (int i = 0; i < 8; i++)
#pragma unroll
                for (int j = 0; j < 4; j++)
                    acc[i][j] = fmaf(ar[i], br[j], acc[i][j]);
        }
    }

    // epilogue
    if (bn + tn < N) {   // N % 4 == 0 so whole float4 is valid when first col is
        float4 bvec = make_float4(0.f, 0.f, 0.f, 0.f);
        if (bias) bvec = *(const float4*)(bias + bn + tn);
#pragma unroll
        for (int i = 0; i < 8; i++) {
            float4 r;
            r.x = acc[i][0] + bvec.x;
            r.y = acc[i][1] + bvec.y;
            r.z = acc[i][2] + bvec.z;
            r.w = acc[i][3] + bvec.w;
            *(float4*)(C + (size_t)(bm + tm + i) * N + bn + tn) = r;
        }
    }
}

// ---------------------------------------------------------------------------
// Per-frame tiny attention: 1 warp per (b,h,n) frame.
// q,k from g_C1, v from g_Vp; writes attention result back into g_Vp[3:147].
// ---------------------------------------------------------------------------
__global__ __launch_bounds__(256) void attn_kernel(const float* __restrict__ C1,
                                                   float* __restrict__ Vp)
{
    __shared__ float s_ka[8][144];
    __shared__ float s_va[8][144];
    __shared__ float s_p[8][24][24];

    const int warp = threadIdx.x >> 5;
    const int lane = threadIdx.x & 31;
    const unsigned w = blockIdx.x * 8u + warp;     // 0 .. 131071
    const int b   = w >> 12;                       // / (HEADS*N_SEQ)
    const int rem = w & 4095;
    const int h   = rem >> 9;
    const int n   = rem & 511;
    const size_t row = (size_t)b * N_SEQ + n;

    const float* qbase = C1 + row * QK_COLS + h * DEPTH + 3;
    const float* kbase = C1 + row * QK_COLS + DH + h * DEPTH + 3;
    float*       vbase = Vp + row * DH + h * DEPTH + 3;

    for (int i = lane; i < 144; i += 32) {
        s_ka[warp][i] = kbase[i];
        s_va[warp][i] = vbase[i];
    }
    float q[6];
    if (lane < 24) {
#pragma unroll
        for (int d = 0; d < 6; d++) q[d] = qbase[lane * 6 + d];
    }
    __syncwarp();

    if (lane < 24) {
        const float scale = 0.4082482904638631f;   // 1/sqrt(6)
        float s[24];
        float mx = -1e30f;
#pragma unroll
        for (int kk = 0; kk < 24; kk++) {
            float a = 0.f;
#pragma unroll
            for (int d = 0; d < 6; d++)
                a = fmaf(q[d], s_ka[warp][kk * 6 + d], a);
            a *= scale;
            s[kk] = a;
            mx = fmaxf(mx, a);
        }
        float sum = 0.f;
#pragma unroll
        for (int kk = 0; kk < 24; kk++) { s[kk] = expf(s[kk] - mx); sum += s[kk]; }
        float inv = 1.0f / sum;
#pragma unroll
        for (int kk = 0; kk < 24; kk++) s_p[warp][lane][kk] = s[kk] * inv;
    }
    __syncwarp();

    if (lane == 0) {
        float (*p)[24] = s_p[warp];
        p[0][6] = (p[0][6] + p[0][3]) * 0.5f;
        p[6][0] = (p[6][0] + p[3][0]) * 0.5f;
        p[0][9] = (p[0][9] + p[0][6]) * 0.5f;
        p[9][0] = (p[9][0] + p[6][0]) * 0.5f;
#pragma unroll
        for (int idx = 12; idx <= 14; idx++) {
            p[0][idx] = (p[0][idx] + p[0][9]) * 0.5f;
            p[idx][0] = (p[idx][0] + p[9][0]) * 0.5f;
        }
        // dict insertion order: (13,16), (14,17), (12,15)
        p[0][16] = (p[0][16] + p[0][13]) * 0.5f;
        p[16][0] = (p[16][0] + p[13][0]) * 0.5f;
        p[0][17] = (p[0][17] + p[0][14]) * 0.5f;
        p[17][0] = (p[17][0] + p[14][0]) * 0.5f;
        p[0][15] = (p[0][15] + p[0][12]) * 0.5f;
        p[15][0] = (p[15][0] + p[12][0]) * 0.5f;
    }
    __syncwarp();

    if (lane < 24) {
        float out[6] = {0.f, 0.f, 0.f, 0.f, 0.f, 0.f};
#pragma unroll
        for (int kk = 0; kk < 24; kk++) {
            float pv = s_p[warp][lane][kk];
#pragma unroll
            for (int d = 0; d < 6; d++)
                out[d] = fmaf(pv, s_va[warp][kk * 6 + d], out[d]);
        }
#pragma unroll
        for (int d = 0; d < 6; d++)
            vbase[lane * 6 + d] = out[d];
    }
}

// ---------------------------------------------------------------------------
extern "C" void kernel_launch(void* const* d_in, const int* in_sizes, int n_in,
                              void* d_out, int out_size)
{
    const float* query = (const float*)d_in[0];
    // d_in[1] = key: IGNORED (reference never uses it)
    const float* value = (const float*)d_in[2];
    const float* qk_w  = (const float*)d_in[3];
    const float* v_w   = (const float*)d_in[4];
    const float* lin_w = (const float*)d_in[5];
    const float* lin_b = (const float*)d_in[6];
    float* out = (float*)d_out;

    float *C1, *Vp;
    cudaGetSymbolAddress((void**)&C1, g_C1);
    cudaGetSymbolAddress((void**)&Vp, g_Vp);

    dim3 blk(256);

    // GEMM1: [16384,512] @ [512,2352] -> C1
    {
        dim3 grid((QK_COLS + BN - 1) / BN, M_ROWS / BM);   // 37 x 128
        gemm_kernel<<<grid, blk>>>(query, qk_w, C1, M_ROWS, QK_COLS, D_MODEL, nullptr);
    }
    // GEMM2: [16384,512] @ [512,1176] -> Vp
    {
        dim3 grid((DH + BN - 1) / BN, M_ROWS / BM);        // 19 x 128
        gemm_kernel<<<grid, blk>>>(value, v_w, Vp, M_ROWS, DH, D_MODEL, nullptr);
    }
    // Attention: 131072 frames, 8 warps/block
    {
        attn_kernel<<<M_ROWS * HEADS / 8, blk>>>(C1, Vp);
    }
    // GEMM3: [16384,1176] @ [1176,512] + bias -> out
    {
        dim3 grid(D_MODEL / BN, M_ROWS / BM);              // 8 x 128
        gemm_kernel<<<grid, blk>>>(Vp, lin_w, out, M_ROWS, D_MODEL, DH, lin_b);
    }
}

// round 4
// speedup vs baseline: 2.0516x; 2.0516x over previous
#include <cuda_runtime.h>
#include <cuda_bf16.h>
#include <cstdint>
#include <math.h>

// ---------------------------------------------------------------- constants
#define B_SZ 32
#define N_SEQ 512
#define D_MODEL 512
#define DEPTH 147
#define HEADS 8
#define DH (DEPTH * HEADS)          // 1176
#define M_ROWS (B_SZ * N_SEQ)       // 16384
#define QK_COLS (2 * DH)            // 2352
#define VP_STRIDE 1184              // 1176 padded so K%32==0 for GEMM3
#define K_G3 1184

// ---------------------------------------------------------------- scratch
__device__ float g_C1[(size_t)M_ROWS * QK_COLS];     // q|k projections
__device__ float g_Vp[(size_t)M_ROWS * VP_STRIDE];   // v projection (padded)
__device__ float g_Wt1[(size_t)QK_COLS * D_MODEL];   // qk_w^T  [2352,512] (tf32)
__device__ float g_Wt2[(size_t)DH * D_MODEL];        // v_w^T   [1176,512] (tf32)
__device__ float g_Wt3[(size_t)D_MODEL * K_G3];      // lin_w^T [512,1184] (tf32, k-padded)

// ---------------------------------------------------------------- helpers
__device__ __forceinline__ float rna_tf32(float x) {
    uint32_t o;
    asm("cvt.rna.tf32.f32 %0, %1;" : "=r"(o) : "f"(x));
    return __uint_as_float(o);
}

__device__ __forceinline__ void mma_tf32(float c[4],
                                         uint32_t a0, uint32_t a1, uint32_t a2, uint32_t a3,
                                         uint32_t b0, uint32_t b1)
{
    asm volatile(
        "mma.sync.aligned.m16n8k8.row.col.f32.tf32.tf32.f32 "
        "{%0,%1,%2,%3}, {%4,%5,%6,%7}, {%8,%9}, {%0,%1,%2,%3};"
        : "+f"(c[0]), "+f"(c[1]), "+f"(c[2]), "+f"(c[3])
        : "r"(a0), "r"(a1), "r"(a2), "r"(a3), "r"(b0), "r"(b1));
}

// ---------------------------------------------------------------- tf32 GEMM
// C[M_ROWS, *] = rna_tf32(A[M_ROWS, KA]) @ Bt[Ncols, KA]^T (+bias)
// Bt already tf32-rounded. CTA tile 128x128, BK=32, 256 threads, warp tile 64x32.
// Columns [Ncols, zeroLimit) are written as 0 (Bs tile zero-filled there).
__global__ __launch_bounds__(256, 1) void gemm_tf32(
    const float* __restrict__ A, const float* __restrict__ Bt, float* __restrict__ C,
    int KA, int Ncols, int Cstride, int zeroLimit, const float* __restrict__ bias)
{
    __shared__ float As[128][36];   // [m][k], pad 36 -> frag banks 4*gr+gc distinct
    __shared__ float Bs[128][36];   // [n][k]

    const int tid  = threadIdx.x;
    const int bm   = blockIdx.y * 128;
    const int bn   = blockIdx.x * 128;
    const int wid  = tid >> 5;
    const int lane = tid & 31;
    const int wm   = (wid & 1) * 64;      // warp m offset
    const int wn   = (wid >> 1) * 32;     // warp n offset
    const int gr   = lane >> 2;           // 0..7
    const int gc   = lane & 3;            // 0..3

    const int lrow = tid >> 3;            // 0..31 (tile row per pass)
    const int lkc  = (tid & 7) * 4;       // 0..28 (k offset, float4)

    float c[4][4][4];
    #pragma unroll
    for (int mt = 0; mt < 4; mt++)
        #pragma unroll
        for (int nt = 0; nt < 4; nt++)
            #pragma unroll
            for (int i = 0; i < 4; i++) c[mt][nt][i] = 0.f;

    for (int k0 = 0; k0 < KA; k0 += 32) {
        // ---- A tile: 128x32, coalesced float4, tf32-round on the fly
        #pragma unroll
        for (int p = 0; p < 4; p++) {
            const int r = lrow + p * 32;
            float4 v = *(const float4*)(A + (size_t)(bm + r) * KA + k0 + lkc);
            v.x = rna_tf32(v.x); v.y = rna_tf32(v.y);
            v.z = rna_tf32(v.z); v.w = rna_tf32(v.w);
            *(float4*)&As[r][lkc] = v;
        }
        // ---- B tile: 128x32 from K-major Bt[N,KA]; zero-fill n >= Ncols
        #pragma unroll
        for (int p = 0; p < 4; p++) {
            const int r = lrow + p * 32;
            const int n = bn + r;
            float4 v = make_float4(0.f, 0.f, 0.f, 0.f);
            if (n < Ncols) v = *(const float4*)(Bt + (size_t)n * KA + k0 + lkc);
            *(float4*)&Bs[r][lkc] = v;
        }
        __syncthreads();

        #pragma unroll
        for (int ks = 0; ks < 4; ks++) {
            const int kb = ks * 8;
            uint32_t af[4][4], bf[4][2];
            #pragma unroll
            for (int mt = 0; mt < 4; mt++) {
                const int m = wm + mt * 16 + gr;
                af[mt][0] = __float_as_uint(As[m    ][kb + gc    ]);
                af[mt][1] = __float_as_uint(As[m + 8][kb + gc    ]);
                af[mt][2] = __float_as_uint(As[m    ][kb + gc + 4]);
                af[mt][3] = __float_as_uint(As[m + 8][kb + gc + 4]);
            }
            #pragma unroll
            for (int nt = 0; nt < 4; nt++) {
                const int n = wn + nt * 8 + gr;
                bf[nt][0] = __float_as_uint(Bs[n][kb + gc    ]);
                bf[nt][1] = __float_as_uint(Bs[n][kb + gc + 4]);
            }
            #pragma unroll
            for (int mt = 0; mt < 4; mt++)
                #pragma unroll
                for (int nt = 0; nt < 4; nt++)
                    mma_tf32(c[mt][nt], af[mt][0], af[mt][1], af[mt][2], af[mt][3],
                             bf[nt][0], bf[nt][1]);
        }
        __syncthreads();
    }

    // ---- epilogue (cols >= Ncols accumulated exactly 0 from zero-filled Bs)
    #pragma unroll
    for (int mt = 0; mt < 4; mt++) {
        const int row = bm + wm + mt * 16 + gr;
        float* Cr0 = C + (size_t)row * Cstride;
        float* Cr1 = C + (size_t)(row + 8) * Cstride;
        #pragma unroll
        for (int nt = 0; nt < 4; nt++) {
            const int col = bn + wn + nt * 8 + 2 * gc;
            if (col < zeroLimit) {
                float b0 = 0.f, b1 = 0.f;
                if (bias && col < Ncols) { b0 = bias[col]; b1 = bias[col + 1]; }
                float2 r0 = make_float2(c[mt][nt][0] + b0, c[mt][nt][1] + b1);
                float2 r1 = make_float2(c[mt][nt][2] + b0, c[mt][nt][3] + b1);
                *(float2*)(Cr0 + col) = r0;
                *(float2*)(Cr1 + col) = r1;
            }
        }
    }
}

// ---------------------------------------------------------------- weight transpose
// Wt[n*Kp + k] = rna_tf32(W[k*N + n]); k in [K, Kp) -> 0
__global__ void transpose_round(const float* __restrict__ W, float* __restrict__ Wt,
                                int K, int N, int Kp)
{
    __shared__ float t[32][33];
    const int nb = blockIdx.x * 32, kb = blockIdx.y * 32;
    for (int i = threadIdx.y; i < 32; i += 8) {
        const int k = kb + i, n = nb + threadIdx.x;
        t[i][threadIdx.x] = (k < K && n < N) ? W[(size_t)k * N + n] : 0.f;
    }
    __syncthreads();
    for (int i = threadIdx.y; i < 32; i += 8) {
        const int n = nb + i, k = kb + threadIdx.x;
        if (n < N && k < Kp) Wt[(size_t)n * Kp + k] = rna_tf32(t[threadIdx.x][i]);
    }
}

// ---------------------------------------------------------------- tiny attention
__global__ __launch_bounds__(256) void attn_kernel(const float* __restrict__ C1,
                                                   float* __restrict__ Vp)
{
    __shared__ float s_ka[8][144];
    __shared__ float s_va[8][144];
    __shared__ float s_p[8][24][24];

    const int warp = threadIdx.x >> 5;
    const int lane = threadIdx.x & 31;
    const unsigned w = blockIdx.x * 8u + warp;     // 0 .. 131071
    const int b   = w >> 12;
    const int rem = w & 4095;
    const int h   = rem >> 9;
    const int n   = rem & 511;
    const size_t row = (size_t)b * N_SEQ + n;

    const float* qbase = C1 + row * QK_COLS + h * DEPTH + 3;
    const float* kbase = C1 + row * QK_COLS + DH + h * DEPTH + 3;
    float*       vbase = Vp + row * VP_STRIDE + h * DEPTH + 3;

    for (int i = lane; i < 144; i += 32) {
        s_ka[warp][i] = kbase[i];
        s_va[warp][i] = vbase[i];
    }
    float q[6];
    if (lane < 24) {
        #pragma unroll
        for (int d = 0; d < 6; d++) q[d] = qbase[lane * 6 + d];
    }
    __syncwarp();

    if (lane < 24) {
        const float scale = 0.4082482904638631f;   // 1/sqrt(6)
        float s[24];
        float mx = -1e30f;
        #pragma unroll
        for (int kk = 0; kk < 24; kk++) {
            float a = 0.f;
            #pragma unroll
            for (int d = 0; d < 6; d++) a = fmaf(q[d], s_ka[warp][kk * 6 + d], a);
            a *= scale;
            s[kk] = a;
            mx = fmaxf(mx, a);
        }
        float sum = 0.f;
        #pragma unroll
        for (int kk = 0; kk < 24; kk++) { s[kk] = expf(s[kk] - mx); sum += s[kk]; }
        const float inv = 1.0f / sum;
        #pragma unroll
        for (int kk = 0; kk < 24; kk++) s_p[warp][lane][kk] = s[kk] * inv;
    }
    __syncwarp();

    if (lane == 0) {
        float (*p)[24] = s_p[warp];
        p[0][6] = (p[0][6] + p[0][3]) * 0.5f;
        p[6][0] = (p[6][0] + p[3][0]) * 0.5f;
        p[0][9] = (p[0][9] + p[0][6]) * 0.5f;
        p[9][0] = (p[9][0] + p[6][0]) * 0.5f;
        #pragma unroll
        for (int idx = 12; idx <= 14; idx++) {
            p[0][idx] = (p[0][idx] + p[0][9]) * 0.5f;
            p[idx][0] = (p[idx][0] + p[9][0]) * 0.5f;
        }
        // dict insertion order: (13,16), (14,17), (12,15)
        p[0][16] = (p[0][16] + p[0][13]) * 0.5f;
        p[16][0] = (p[16][0] + p[13][0]) * 0.5f;
        p[0][17] = (p[0][17] + p[0][14]) * 0.5f;
        p[17][0] = (p[17][0] + p[14][0]) * 0.5f;
        p[0][15] = (p[0][15] + p[0][12]) * 0.5f;
        p[15][0] = (p[15][0] + p[12][0]) * 0.5f;
    }
    __syncwarp();

    if (lane < 24) {
        float out[6] = {0.f, 0.f, 0.f, 0.f, 0.f, 0.f};
        #pragma unroll
        for (int kk = 0; kk < 24; kk++) {
            const float pv = s_p[warp][lane][kk];
            #pragma unroll
            for (int d = 0; d < 6; d++) out[d] = fmaf(pv, s_va[warp][kk * 6 + d], out[d]);
        }
        #pragma unroll
        for (int d = 0; d < 6; d++) vbase[lane * 6 + d] = out[d];
    }
}

// ---------------------------------------------------------------- host
extern "C" void kernel_launch(void* const* d_in, const int* in_sizes, int n_in,
                              void* d_out, int out_size)
{
    const float* query = (const float*)d_in[0];
    // d_in[1] = key: ignored by the reference
    const float* value = (const float*)d_in[2];
    const float* qk_w  = (const float*)d_in[3];
    const float* v_w   = (const float*)d_in[4];
    const float* lin_w = (const float*)d_in[5];
    const float* lin_b = (const float*)d_in[6];
    float* out = (float*)d_out;

    float *C1, *Vp, *Wt1, *Wt2, *Wt3;
    cudaGetSymbolAddress((void**)&C1, g_C1);
    cudaGetSymbolAddress((void**)&Vp, g_Vp);
    cudaGetSymbolAddress((void**)&Wt1, g_Wt1);
    cudaGetSymbolAddress((void**)&Wt2, g_Wt2);
    cudaGetSymbolAddress((void**)&Wt3, g_Wt3);

    // 1) transpose + tf32-round weights into K-major [N, K]
    {
        dim3 blk(32, 8);
        transpose_round<<<dim3((QK_COLS + 31) / 32, (D_MODEL + 31) / 32), blk>>>(
            qk_w, Wt1, D_MODEL, QK_COLS, D_MODEL);
        transpose_round<<<dim3((DH + 31) / 32, (D_MODEL + 31) / 32), blk>>>(
            v_w, Wt2, D_MODEL, DH, D_MODEL);
        transpose_round<<<dim3((D_MODEL + 31) / 32, (K_G3 + 31) / 32), blk>>>(
            lin_w, Wt3, DH, D_MODEL, K_G3);
    }

    // 2) GEMM1: C1[16384,2352] = rna(query) @ Wt1^T
    gemm_tf32<<<dim3(19, M_ROWS / 128), 256>>>(
        query, Wt1, C1, D_MODEL, QK_COLS, QK_COLS, QK_COLS, nullptr);

    // 3) GEMM2: Vp[16384,1184] = rna(value) @ Wt2^T  (cols 1176..1183 zeroed)
    gemm_tf32<<<dim3(10, M_ROWS / 128), 256>>>(
        value, Wt2, Vp, D_MODEL, DH, VP_STRIDE, VP_STRIDE, nullptr);

    // 4) tiny per-frame attention (fp32, in-place on Vp)
    attn_kernel<<<M_ROWS * HEADS / 8, 256>>>(C1, Vp);

    // 5) GEMM3: out[16384,512] = rna(Vp) @ Wt3^T + bias
    gemm_tf32<<<dim3(4, M_ROWS / 128), 256>>>(
        Vp, Wt3, out, K_G3, D_MODEL, D_MODEL, D_MODEL, lin_b);
}